// round 4
// baseline (speedup 1.0000x reference)
#include <cuda_runtime.h>
#include <cstdint>

#define TILE    128
#define TSTEPS  10
#define HID     50
#define NT      25        // 200 gate-cols / 8
#define THREADS 256
#define NCTA    1024      // 131072 / 128
#define AST     132       // padded A k-stride (conflict-free)

// per-CTA-contiguous scratch: [cta][t][j][m] (m fastest)
__device__ float g_scr[NCTA * TSTEPS * HID * TILE];

#define WSM_F2     (25 * 16 * 32)        // 12800 float2 = 102400 B
#define BIAS_OFF   102400
#define A_OFF      103200
#define SMEM_TOTAL (A_OFF + TILE * AST * 4)   // 170784 B

__device__ __forceinline__ float tf32r(float v) {
    uint32_t u; asm("cvt.rna.tf32.f32 %0, %1;" : "=r"(u) : "f"(v));
    return __uint_as_float(u);
}
__device__ __forceinline__ float sigmf(float v) {
    return __fdividef(1.0f, 1.0f + __expf(-v));
}
__device__ __forceinline__ float tanhf_acc(float v) {
    return 1.0f - __fdividef(2.0f, __expf(2.0f * v) + 1.0f);
}
__device__ __forceinline__ void mma8(float (&d)[4], uint32_t a0, uint32_t a1,
                                     uint32_t a2, uint32_t a3, uint32_t b0, uint32_t b1) {
    asm volatile("mma.sync.aligned.m16n8k8.row.col.f32.tf32.tf32.f32 "
                 "{%0,%1,%2,%3}, {%4,%5,%6,%7}, {%8,%9}, {%0,%1,%2,%3};\n"
                 : "+f"(d[0]), "+f"(d[1]), "+f"(d[2]), "+f"(d[3])
                 : "r"(a0), "r"(a1), "r"(a2), "r"(a3), "r"(b0), "r"(b1));
}

__global__ void __launch_bounds__(THREADS, 1)
lstm_fused(const float* __restrict__ x,
           const float* __restrict__ W0, const float* __restrict__ U0, const float* __restrict__ B0,
           const float* __restrict__ W1, const float* __restrict__ U1, const float* __restrict__ B1,
           const float* __restrict__ W2, const float* __restrict__ U2, const float* __restrict__ B2,
           const float* __restrict__ W3, const float* __restrict__ U3, const float* __restrict__ B3,
           const float* __restrict__ Wd1, const float* __restrict__ bd1,
           const float* __restrict__ Wd2, const float* __restrict__ bd2,
           float* __restrict__ out)
{
    extern __shared__ char smem[];
    float2* wsm   = reinterpret_cast<float2*>(smem);
    float*  biasp = reinterpret_cast<float*>(smem + BIAS_OFF);
    float*  A     = reinterpret_cast<float*>(smem + A_OFF);

    const int tid  = threadIdx.x;
    const int lane = tid & 31;
    const int wrp  = tid >> 5;
    const int g    = lane >> 2;
    const int lam  = lane & 3;
    const int cta  = blockIdx.x;
    const int row0 = wrp * 16 + g;
    const int sbase = cta * (TSTEPS * HID * TILE);

    const float* Wl[4] = {W0, W1, W2, W3};
    const float* Ul[4] = {U0, U1, U2, U3};
    const float* bl[4] = {B0, B1, B2, B3};

    for (int l = 0; l < 4; ++l) {
        __syncthreads();                       // prior layer done with wsm/A
        const int Fin = (l == 0) ? 5 : HID;

        // ---- permuted weight fragments: col' = 4j+q, rows [W pad64 ; U pad64] ----
        for (int idx = tid; idx < WSM_F2; idx += THREADS) {
            int ln = idx & 31, kt = (idx >> 5) & 15, nt = idx >> 9;
            int colp = nt * 8 + (ln >> 2);
            int sc   = (colp & 3) * HID + (colp >> 2);   // q*50+j
            int k0   = kt * 8 + (ln & 3), k1 = k0 + 4;
            float v0 = 0.f, v1 = 0.f;
            if (k0 < 64) { if (k0 < Fin) v0 = Wl[l][k0 * 200 + sc]; }
            else if (k0 - 64 < HID)      v0 = Ul[l][(k0 - 64) * 200 + sc];
            if (k1 < 64) { if (k1 < Fin) v1 = Wl[l][k1 * 200 + sc]; }
            else if (k1 - 64 < HID)      v1 = Ul[l][(k1 - 64) * 200 + sc];
            wsm[idx] = make_float2(tf32r(v0), tf32r(v1));
        }
        for (int c = tid; c < 200; c += THREADS)
            biasp[c] = bl[l][(c & 3) * HID + (c >> 2)];
        for (int idx = tid; idx < TILE * AST; idx += THREADS) A[idx] = 0.f;

        float cst[NT];
        #pragma unroll
        for (int nt = 0; nt < NT; ++nt) cst[nt] = 0.f;

        const bool isL0 = (l == 0);

        for (int t = 0; t < TSTEPS; ++t) {
            __syncthreads();                   // epilogue/init writes visible
            // ---- fill input cols of A ----
            if (isL0) {
                for (int idx = tid; idx < TILE * 5; idx += THREADS) {
                    int m = idx / 5, f = idx - m * 5;
                    A[m * AST + f] = tf32r(x[(cta * TILE + m) * 50 + t * 5 + f]);
                }
            } else {
                const float* sp = g_scr + sbase + t * (HID * TILE);
                for (int idx = tid; idx < TILE * HID; idx += THREADS) {
                    int j = idx >> 7, m = idx & 127;
                    A[m * AST + j] = tf32r(sp[j * TILE + m]);
                }
            }
            __syncthreads();

            // ---- hoist a-fragments (k-tiles 0..6, 8..14; 7 & 15 are all-zero pad) ----
            uint32_t af[14][4];
            #pragma unroll
            for (int kk = 0; kk < 14; ++kk) {
                const int kt = (kk < 7) ? kk : kk + 1;
                const float* ap = A + kt * 8 + lam;
                af[kk][0] = __float_as_uint(ap[row0 * AST]);
                af[kk][1] = __float_as_uint(ap[(row0 + 8) * AST]);
                af[kk][2] = __float_as_uint(ap[row0 * AST + 4]);
                af[kk][3] = __float_as_uint(ap[(row0 + 8) * AST + 4]);
            }

            const bool hi = lam & 1;
            const int  row = row0 + (hi ? 8 : 0);
            const float2* wbase = wsm + lane;

            #pragma unroll 1
            for (int nt = 0; nt < NT; ++nt) {
                float2 bv = *reinterpret_cast<const float2*>(&biasp[nt * 8 + lam * 2]);
                float acc[4] = {bv.x, bv.y, bv.x, bv.y};
                const float2* wp = wbase + nt * 512;
                #pragma unroll
                for (int kk = 0; kk < 14; ++kk) {
                    if (isL0 && kk >= 1 && kk < 7) continue;  // zero x-pad tiles
                    const int kt = (kk < 7) ? kk : kk + 1;
                    float2 bb = wp[kt * 32];
                    mma8(acc, af[kk][0], af[kk][1], af[kk][2], af[kk][3],
                         __float_as_uint(bb.x), __float_as_uint(bb.y));
                }
                // ---- gate epilogue: lane ends owning one (row, unit) ----
                float p0 = __shfl_xor_sync(0xffffffffu, acc[0], 1);
                float p1 = __shfl_xor_sync(0xffffffffu, acc[1], 1);
                float p2 = __shfl_xor_sync(0xffffffffu, acc[2], 1);
                float p3 = __shfl_xor_sync(0xffffffffu, acc[3], 1);
                float zi = hi ? p2 : acc[0];
                float zf = hi ? p3 : acc[1];
                float zg = hi ? acc[2] : p0;
                float zo = hi ? acc[3] : p1;
                float c  = sigmf(zf) * cst[nt] + sigmf(zi) * tanhf_acc(zg);
                cst[nt]  = c;
                float h  = sigmf(zo) * tanhf_acc(c);
                int unit = nt * 2 + (lam >> 1);
                if (l == 3) {
                    if (t == TSTEPS - 1) A[row * AST + unit] = h;       // fp32 for dense
                    else                 A[row * AST + 64 + unit] = tf32r(h);
                } else {
                    A[row * AST + 64 + unit] = tf32r(h);
                    g_scr[sbase + (t * HID + unit) * TILE + row] = h;
                }
            }
        }
    }

    // ---- fused dense head ----
    __syncthreads();
    float* dw = reinterpret_cast<float*>(smem);   // reuse weight region
    for (int idx = tid; idx < 2500; idx += THREADS)
        dw[idx] = Wd1[(idx % 50) * 50 + idx / 50];          // dw[j2*50+j]=Wd1[j][j2]
    if (tid < 50) { dw[2500 + tid] = bd1[tid]; dw[2550 + tid] = Wd2[tid]; }
    if (tid == 0)  dw[2600] = bd2[0];
    __syncthreads();

    if (tid < TILE) {
        float h[HID];
        #pragma unroll
        for (int j = 0; j < HID; ++j) h[j] = A[tid * AST + j];
        float acc2 = dw[2600];
        for (int j2 = 0; j2 < HID; ++j2) {
            float a = dw[2500 + j2];
            #pragma unroll
            for (int j = 0; j < HID; ++j) a += h[j] * dw[j2 * 50 + j];
            acc2 += a * dw[2550 + j2];
        }
        out[cta * TILE + tid] = sigmf(acc2);
    }
}

extern "C" void kernel_launch(void* const* d_in, const int* in_sizes, int n_in,
                              void* d_out, int out_size) {
    cudaFuncSetAttribute(lstm_fused, cudaFuncAttributeMaxDynamicSharedMemorySize, SMEM_TOTAL);
    lstm_fused<<<NCTA, THREADS, SMEM_TOTAL>>>(
        (const float*)d_in[0],
        (const float*)d_in[1],  (const float*)d_in[2],  (const float*)d_in[3],
        (const float*)d_in[4],  (const float*)d_in[5],  (const float*)d_in[6],
        (const float*)d_in[7],  (const float*)d_in[8],  (const float*)d_in[9],
        (const float*)d_in[10], (const float*)d_in[11], (const float*)d_in[12],
        (const float*)d_in[13], (const float*)d_in[14],
        (const float*)d_in[15], (const float*)d_in[16],
        (float*)d_out);
}

// round 5
// speedup vs baseline: 2.4549x; 2.4549x over previous
#include <cuda_runtime.h>
#include <cuda_bf16.h>
#include <cstdint>

#define TILE    128
#define TSTEPS  10
#define HID     50
#define THREADS 512
#define NCTA    1024            // 131072 / 128
#define AST     136             // bf16 elems per A row (272B, conflict-free: 68 words, 68%32=4)
#define LSCR    (TSTEPS * HID * TILE)

// single scratch buffer: slot t is read (into A) before it is overwritten (epilogue), per step
__device__ float g_scr[(size_t)NCTA * LSCR];

#define WSM_U2     (25 * 8 * 32)          // 6400 uint2 = 51200 B
#define BIAS_OFF   51200
#define A_OFF      52000
#define SMEM_TOTAL (A_OFF + TILE * AST * 2)   // 52000 + 34816 = 86816 B

__device__ __forceinline__ float sigmf(float v) {
    return __fdividef(1.f, 1.f + __expf(-v));
}
__device__ __forceinline__ float tanha(float v) {
    return 1.f - __fdividef(2.f, __expf(2.f * v) + 1.f);
}
__device__ __forceinline__ uint32_t pack_bf2(float lo, float hi) {
    __nv_bfloat162 p = __floats2bfloat162_rn(lo, hi);   // .x = lo = lower 16 bits
    return *reinterpret_cast<uint32_t*>(&p);
}
__device__ __forceinline__ void mma16(float (&d)[4], const uint32_t (&a)[4], uint2 b) {
    asm volatile("mma.sync.aligned.m16n8k16.row.col.f32.bf16.bf16.f32 "
                 "{%0,%1,%2,%3}, {%4,%5,%6,%7}, {%8,%9}, {%0,%1,%2,%3};\n"
                 : "+f"(d[0]), "+f"(d[1]), "+f"(d[2]), "+f"(d[3])
                 : "r"(a[0]), "r"(a[1]), "r"(a[2]), "r"(a[3]), "r"(b.x), "r"(b.y));
}

__device__ __forceinline__ float fetchWU(int k, int sc, const float* W, const float* U, int Fin) {
    if (k < 64) return (k < Fin) ? W[k * 200 + sc] : 0.f;
    int ku = k - 64;
    return (ku < HID) ? U[ku * 200 + sc] : 0.f;
}

// weights pre-permuted into m16n8k16 b-fragment order, gate cols permuted col' = 4j+q,
// k rows stacked [W pad to 64 ; U pad to 64]; also fills permuted bias and zeroes A.
__device__ __forceinline__ void fill_layer_weights(char* smem, const float* __restrict__ W,
                                                   const float* __restrict__ U,
                                                   const float* __restrict__ b,
                                                   int Fin, int tid)
{
    uint2*    wsm   = reinterpret_cast<uint2*>(smem);
    float*    biasp = reinterpret_cast<float*>(smem + BIAS_OFF);
    uint32_t* Az    = reinterpret_cast<uint32_t*>(smem + A_OFF);
    for (int idx = tid; idx < WSM_U2; idx += THREADS) {
        int lane = idx & 31, kt = (idx >> 5) & 7, nt = idx >> 8;
        int colp = nt * 8 + (lane >> 2);
        int sc   = (colp & 3) * HID + (colp >> 2);      // original col q*50+j
        int kb   = kt * 16 + (lane & 3) * 2;
        float v0 = fetchWU(kb,     sc, W, U, Fin);
        float v1 = fetchWU(kb + 1, sc, W, U, Fin);
        float v2 = fetchWU(kb + 8, sc, W, U, Fin);
        float v3 = fetchWU(kb + 9, sc, W, U, Fin);
        wsm[idx] = make_uint2(pack_bf2(v0, v1), pack_bf2(v2, v3));
    }
    for (int c = tid; c < 200; c += THREADS)
        biasp[c] = b[(c & 3) * HID + (c >> 2)];
    for (int idx = tid; idx < TILE * AST / 2; idx += THREADS)
        Az[idx] = 0u;                                    // zero A (pads + h0 = 0)
}

template<bool L0, bool LAST>
__device__ __forceinline__ void run_layer(char* smem, const float* __restrict__ src,
                                          float* __restrict__ scr, int tid)
{
    const uint2*   wsm   = reinterpret_cast<const uint2*>(smem);
    const float*   biasp = reinterpret_cast<const float*>(smem + BIAS_OFF);
    __nv_bfloat16* A     = reinterpret_cast<__nv_bfloat16*>(smem + A_OFF);

    const int lane = tid & 31, wrp = tid >> 5;
    const int g = lane >> 2, lam = lane & 3;
    const int mw = wrp >> 1, ng = wrp & 1;        // 8 M-tiles x 2 N-halves
    const int row0  = mw * 16 + g;
    const int ntbeg = ng ? 13 : 0;
    const int ntend = ng ? 25 : 13;
    const bool hi   = lam & 1;
    const int rowE  = row0 + (hi ? 8 : 0);

    float cst[13];
#pragma unroll
    for (int i = 0; i < 13; ++i) cst[i] = 0.f;

    for (int t = 0; t < TSTEPS; ++t) {
        __syncthreads();                           // prior writes (weights/zero/epilogue) visible
        if (L0) {
            for (int idx = tid; idx < TILE * 5; idx += THREADS) {
                int m = idx / 5, f = idx - m * 5;
                A[m * AST + f] = __float2bfloat16_rn(src[m * 50 + t * 5 + f]);
            }
        } else {
            const float* sp = src + t * (HID * TILE);
            for (int idx = tid; idx < TILE * HID; idx += THREADS) {
                int j = idx >> 7, m = idx & 127;
                A[m * AST + j] = __float2bfloat16_rn(sp[j * TILE + m]);
            }
        }
        __syncthreads();

        // hoist a-fragments (L0: only k-tiles {0,4..7} are nonzero)
        uint32_t af[8][4];
#pragma unroll
        for (int kt = 0; kt < 8; ++kt) {
            if (L0 && kt >= 1 && kt <= 3) continue;
            const __nv_bfloat16* ap = A + kt * 16 + lam * 2;
            af[kt][0] = *reinterpret_cast<const uint32_t*>(ap + row0 * AST);
            af[kt][1] = *reinterpret_cast<const uint32_t*>(ap + (row0 + 8) * AST);
            af[kt][2] = *reinterpret_cast<const uint32_t*>(ap + row0 * AST + 8);
            af[kt][3] = *reinterpret_cast<const uint32_t*>(ap + (row0 + 8) * AST + 8);
        }
        __syncthreads();                           // all a-frag reads done before h rewritten

        for (int nt = ntbeg; nt < ntend; ++nt) {
            float2 bv = *reinterpret_cast<const float2*>(&biasp[nt * 8 + lam * 2]);
            float accA[4] = {bv.x, bv.y, bv.x, bv.y};
            float accB[4] = {0.f, 0.f, 0.f, 0.f};
            const uint2* wp = wsm + nt * 256 + lane;
#pragma unroll
            for (int kt = 0; kt < 8; ++kt) {
                if (L0 && kt >= 1 && kt <= 3) continue;
                uint2 bb = wp[kt * 32];
                if (kt & 1) mma16(accB, af[kt], bb);
                else        mma16(accA, af[kt], bb);
            }
            float a0 = accA[0] + accB[0], a1 = accA[1] + accB[1];
            float a2 = accA[2] + accB[2], a3 = accA[3] + accB[3];
            // pair-exchange so each lane owns one (row, unit) with all 4 gates
            float p0 = __shfl_xor_sync(0xffffffffu, a0, 1);
            float p1 = __shfl_xor_sync(0xffffffffu, a1, 1);
            float p2 = __shfl_xor_sync(0xffffffffu, a2, 1);
            float p3 = __shfl_xor_sync(0xffffffffu, a3, 1);
            float zi = hi ? p2 : a0;
            float zf = hi ? p3 : a1;
            float zg = hi ? a2 : p0;
            float zo = hi ? a3 : p1;
            float c  = sigmf(zf) * cst[nt - ntbeg] + sigmf(zi) * tanha(zg);
            cst[nt - ntbeg] = c;
            float h  = sigmf(zo) * tanha(c);
            int unit = nt * 2 + (lam >> 1);
            if (LAST) {
                if (t == TSTEPS - 1) scr[(t * HID + unit) * TILE + rowE] = h;   // fp32 for dense
                else                 A[rowE * AST + 64 + unit] = __float2bfloat16_rn(h);
            } else {
                A[rowE * AST + 64 + unit] = __float2bfloat16_rn(h);
                scr[(t * HID + unit) * TILE + rowE] = h;
            }
        }
    }
}

__global__ void __launch_bounds__(THREADS)
lstm_fused(const float* __restrict__ x,
           const float* __restrict__ W0, const float* __restrict__ U0, const float* __restrict__ B0,
           const float* __restrict__ W1, const float* __restrict__ U1, const float* __restrict__ B1,
           const float* __restrict__ W2, const float* __restrict__ U2, const float* __restrict__ B2,
           const float* __restrict__ W3, const float* __restrict__ U3, const float* __restrict__ B3,
           const float* __restrict__ Wd1, const float* __restrict__ bd1,
           const float* __restrict__ Wd2, const float* __restrict__ bd2,
           float* __restrict__ out)
{
    extern __shared__ char smem[];
    const int tid = threadIdx.x;
    const int cta = blockIdx.x;
    float* scr = g_scr + (size_t)cta * LSCR;

    fill_layer_weights(smem, W0, U0, B0, 5, tid);
    run_layer<true,  false>(smem, x + (size_t)cta * TILE * 50, scr, tid);
    __syncthreads();
    fill_layer_weights(smem, W1, U1, B1, HID, tid);
    run_layer<false, false>(smem, scr, scr, tid);
    __syncthreads();
    fill_layer_weights(smem, W2, U2, B2, HID, tid);
    run_layer<false, false>(smem, scr, scr, tid);
    __syncthreads();
    fill_layer_weights(smem, W3, U3, B3, HID, tid);
    run_layer<false, true >(smem, scr, scr, tid);
    __syncthreads();

    // fused dense head: out = sigmoid((h @ Wd1 + bd1) @ Wd2 + bd2)
    float* dw = reinterpret_cast<float*>(smem);          // reuse weight region
    for (int idx = tid; idx < 2500; idx += THREADS)
        dw[idx] = Wd1[(idx % 50) * 50 + idx / 50];       // dw[j2*50+j] = Wd1[j][j2]
    if (tid < 50) { dw[2500 + tid] = bd1[tid]; dw[2550 + tid] = Wd2[tid]; }
    if (tid == 0)  dw[2600] = bd2[0];
    __syncthreads();

    if (tid < TILE) {
        const float* hp = scr + 9 * HID * TILE + tid;    // layer-4 last h (fp32)
        float h[HID];
#pragma unroll
        for (int j = 0; j < HID; ++j) h[j] = hp[j * TILE];
        float acc2 = dw[2600];
        for (int j2 = 0; j2 < HID; ++j2) {
            float a = dw[2500 + j2];
#pragma unroll
            for (int j = 0; j < HID; ++j) a += h[j] * dw[j2 * 50 + j];
            acc2 += a * dw[2550 + j2];
        }
        out[cta * TILE + tid] = sigmf(acc2);
    }
}

extern "C" void kernel_launch(void* const* d_in, const int* in_sizes, int n_in,
                              void* d_out, int out_size) {
    cudaFuncSetAttribute(lstm_fused, cudaFuncAttributeMaxDynamicSharedMemorySize, SMEM_TOTAL);
    lstm_fused<<<NCTA, THREADS, SMEM_TOTAL>>>(
        (const float*)d_in[0],
        (const float*)d_in[1],  (const float*)d_in[2],  (const float*)d_in[3],
        (const float*)d_in[4],  (const float*)d_in[5],  (const float*)d_in[6],
        (const float*)d_in[7],  (const float*)d_in[8],  (const float*)d_in[9],
        (const float*)d_in[10], (const float*)d_in[11], (const float*)d_in[12],
        (const float*)d_in[13], (const float*)d_in[14],
        (const float*)d_in[15], (const float*)d_in[16],
        (float*)d_out);
}